// round 1
// baseline (speedup 1.0000x reference)
#include <cuda_runtime.h>
#include <math_constants.h>

// Problem constants
#define S_LEN   4096
#define D_MODEL 512
#define H_NUM   8
#define HD      64
#define LDQKV   1536      // 3*D_MODEL

// Scratch (no cudaMalloc allowed)
__device__ float g_qkv[S_LEN * LDQKV];    // [4096,1536]  Q|K|V
__device__ float g_attn[S_LEN * D_MODEL]; // [4096,512]   attention output (head-merged)

// ---------------------------------------------------------------------------
// GEMM: C[M,N] = A[M,K] @ B[N,K]^T + bias[N]
// 128x128 block tile, 256 threads, 8x8 per thread, K-tile 16.
// Smem tiles stored transposed (As[k][m], Bs[k][n]) so the compute phase does
// broadcast (A) and stride-16B float4 (B) conflict-free LDS.
// Requires M%128==0, N%128==0, K%16==0 (true for all our shapes).
// ---------------------------------------------------------------------------
__global__ __launch_bounds__(256) void gemm_bias_kernel(
    const float* __restrict__ A, const float* __restrict__ B,
    const float* __restrict__ bias, float* __restrict__ C,
    int M, int N, int K)
{
    __shared__ float As[16][132];
    __shared__ float Bs[16][132];

    const int tid = threadIdx.x;
    const int tx  = tid & 15;
    const int ty  = tid >> 4;
    const int m0  = blockIdx.y * 128;
    const int n0  = blockIdx.x * 128;

    float acc[8][8];
#pragma unroll
    for (int i = 0; i < 8; i++)
#pragma unroll
        for (int j = 0; j < 8; j++) acc[i][j] = 0.0f;

    for (int k0 = 0; k0 < K; k0 += 16) {
#pragma unroll
        for (int i = 0; i < 2; i++) {
            int f   = tid + i * 256;   // float4 index 0..511
            int row = f >> 2;          // 0..127
            int kq  = (f & 3) << 2;    // 0,4,8,12
            float4 a = *(const float4*)(A + (size_t)(m0 + row) * K + k0 + kq);
            As[kq + 0][row] = a.x; As[kq + 1][row] = a.y;
            As[kq + 2][row] = a.z; As[kq + 3][row] = a.w;
            float4 b = *(const float4*)(B + (size_t)(n0 + row) * K + k0 + kq);
            Bs[kq + 0][row] = b.x; Bs[kq + 1][row] = b.y;
            Bs[kq + 2][row] = b.z; Bs[kq + 3][row] = b.w;
        }
        __syncthreads();

#pragma unroll
        for (int kk = 0; kk < 16; kk++) {
            float ra[8], rb[8];
            *(float4*)&ra[0] = *(const float4*)&As[kk][ty * 4];
            *(float4*)&ra[4] = *(const float4*)&As[kk][64 + ty * 4];
            *(float4*)&rb[0] = *(const float4*)&Bs[kk][tx * 4];
            *(float4*)&rb[4] = *(const float4*)&Bs[kk][64 + tx * 4];
#pragma unroll
            for (int i = 0; i < 8; i++)
#pragma unroll
                for (int j = 0; j < 8; j++)
                    acc[i][j] = fmaf(ra[i], rb[j], acc[i][j]);
        }
        __syncthreads();
    }

#pragma unroll
    for (int ih = 0; ih < 2; ih++)
#pragma unroll
        for (int r = 0; r < 4; r++) {
            int row = m0 + ih * 64 + ty * 4 + r;
#pragma unroll
            for (int jh = 0; jh < 2; jh++) {
                int col = n0 + jh * 64 + tx * 4;
                float4 bv = *(const float4*)(bias + col);
                float4 o;
                o.x = acc[ih * 4 + r][jh * 4 + 0] + bv.x;
                o.y = acc[ih * 4 + r][jh * 4 + 1] + bv.y;
                o.z = acc[ih * 4 + r][jh * 4 + 2] + bv.z;
                o.w = acc[ih * 4 + r][jh * 4 + 3] + bv.w;
                *(float4*)(C + (size_t)row * N + col) = o;
            }
        }
}

// ---------------------------------------------------------------------------
// Flash attention, fp32 SIMT. Br=Bc=64, Hd=64. One CTA per (q-block, head).
// 256 threads as 16x16, each owns a 4x4 tile of the 64x64 score block and a
// 4(row)x4(col) slice of the O accumulator. Online softmax with per-row m,l
// kept redundantly in the 16 threads sharing a row-group (shfl reductions).
// ---------------------------------------------------------------------------
#define FPAD 68
#define FLASH_SMEM (4 * 64 * FPAD * 4)   // Qt,Kt,Vs,Ps -> 69632 bytes

__global__ __launch_bounds__(256, 2) void flash_attn_kernel(
    const float* __restrict__ qkv, float* __restrict__ attn_out)
{
    extern __shared__ float sm[];
    float* Qt = sm;                  // [64][FPAD]  Qt[d][i]
    float* Kt = sm + 64 * FPAD;      // [64][FPAD]  Kt[d][j]
    float* Vs = sm + 2 * 64 * FPAD;  // [64][FPAD]  Vs[k][j]
    float* Ps = sm + 3 * 64 * FPAD;  // [64][FPAD]  Ps[i][k]

    const int tid = threadIdx.x;
    const int tx  = tid & 15;
    const int ty  = tid >> 4;
    const int h   = blockIdx.y;
    const int q0  = blockIdx.x * 64;
    const int col = h * HD;

    // Load Q tile transposed: Qt[d][i]
#pragma unroll
    for (int i = 0; i < 4; i++) {
        int f   = tid + i * 256;   // 0..1023 float4 idx
        int row = f >> 4;          // 0..63
        int d4  = (f & 15) << 2;   // 0..60
        float4 a = *(const float4*)(qkv + (size_t)(q0 + row) * LDQKV + col + d4);
        Qt[(d4 + 0) * FPAD + row] = a.x;
        Qt[(d4 + 1) * FPAD + row] = a.y;
        Qt[(d4 + 2) * FPAD + row] = a.z;
        Qt[(d4 + 3) * FPAD + row] = a.w;
    }

    float  m_run[4], l_run[4];
    float4 o4[4];
#pragma unroll
    for (int r = 0; r < 4; r++) {
        m_run[r] = -CUDART_INF_F;
        l_run[r] = 0.0f;
        o4[r]    = make_float4(0.f, 0.f, 0.f, 0.f);
    }

    for (int k0 = 0; k0 < S_LEN; k0 += 64) {
        __syncthreads();  // previous iter's Ps/Vs reads done (also covers Qt first time)
#pragma unroll
        for (int i = 0; i < 4; i++) {
            int f   = tid + i * 256;
            int row = f >> 4;
            int d4  = (f & 15) << 2;
            const float* base = qkv + (size_t)(k0 + row) * LDQKV + col + d4;
            float4 kv = *(const float4*)(base + D_MODEL);       // K
            Kt[(d4 + 0) * FPAD + row] = kv.x;
            Kt[(d4 + 1) * FPAD + row] = kv.y;
            Kt[(d4 + 2) * FPAD + row] = kv.z;
            Kt[(d4 + 3) * FPAD + row] = kv.w;
            float4 vv = *(const float4*)(base + 2 * D_MODEL);   // V
            *(float4*)(Vs + row * FPAD + d4) = vv;
        }
        __syncthreads();

        // S = (Q K^T) * scale  — each thread: rows ty*4.., cols tx*4..
        float s[4][4];
#pragma unroll
        for (int r = 0; r < 4; r++)
#pragma unroll
            for (int c = 0; c < 4; c++) s[r][c] = 0.0f;

#pragma unroll 8
        for (int d = 0; d < 64; d++) {
            float qa[4], kb[4];
            *(float4*)qa = *(const float4*)(Qt + d * FPAD + ty * 4);
            *(float4*)kb = *(const float4*)(Kt + d * FPAD + tx * 4);
#pragma unroll
            for (int r = 0; r < 4; r++)
#pragma unroll
                for (int c = 0; c < 4; c++)
                    s[r][c] = fmaf(qa[r], kb[c], s[r][c]);
        }
        const float scale = 0.125f;  // 1/sqrt(64)
#pragma unroll
        for (int r = 0; r < 4; r++)
#pragma unroll
            for (int c = 0; c < 4; c++) s[r][c] *= scale;

        // Online softmax update (per row, reduced across the 16 tx threads)
#pragma unroll
        for (int r = 0; r < 4; r++) {
            float lm = fmaxf(fmaxf(s[r][0], s[r][1]), fmaxf(s[r][2], s[r][3]));
            lm = fmaxf(lm, __shfl_xor_sync(0xffffffffu, lm, 8));
            lm = fmaxf(lm, __shfl_xor_sync(0xffffffffu, lm, 4));
            lm = fmaxf(lm, __shfl_xor_sync(0xffffffffu, lm, 2));
            lm = fmaxf(lm, __shfl_xor_sync(0xffffffffu, lm, 1));
            float mn    = fmaxf(m_run[r], lm);
            float alpha = __expf(m_run[r] - mn);   // exp(-inf)=0 on first tile
            m_run[r] = mn;

            float p0 = __expf(s[r][0] - mn);
            float p1 = __expf(s[r][1] - mn);
            float p2 = __expf(s[r][2] - mn);
            float p3 = __expf(s[r][3] - mn);
            float ts = (p0 + p1) + (p2 + p3);
            ts += __shfl_xor_sync(0xffffffffu, ts, 8);
            ts += __shfl_xor_sync(0xffffffffu, ts, 4);
            ts += __shfl_xor_sync(0xffffffffu, ts, 2);
            ts += __shfl_xor_sync(0xffffffffu, ts, 1);
            l_run[r] = l_run[r] * alpha + ts;

            o4[r].x *= alpha; o4[r].y *= alpha;
            o4[r].z *= alpha; o4[r].w *= alpha;

            float4 pv = make_float4(p0, p1, p2, p3);
            *(float4*)(Ps + (ty * 4 + r) * FPAD + tx * 4) = pv;
        }
        __syncthreads();

        // O += P @ V
#pragma unroll 8
        for (int k = 0; k < 64; k++) {
            float4 v4 = *(const float4*)(Vs + k * FPAD + tx * 4);
#pragma unroll
            for (int r = 0; r < 4; r++) {
                float pr = Ps[(ty * 4 + r) * FPAD + k];
                o4[r].x = fmaf(pr, v4.x, o4[r].x);
                o4[r].y = fmaf(pr, v4.y, o4[r].y);
                o4[r].z = fmaf(pr, v4.z, o4[r].z);
                o4[r].w = fmaf(pr, v4.w, o4[r].w);
            }
        }
    }

#pragma unroll
    for (int r = 0; r < 4; r++) {
        float inv = 1.0f / l_run[r];
        float4 o  = o4[r];
        o.x *= inv; o.y *= inv; o.z *= inv; o.w *= inv;
        *(float4*)(attn_out + (size_t)(q0 + ty * 4 + r) * D_MODEL + col + tx * 4) = o;
    }
}

// ---------------------------------------------------------------------------
// Launch: QKV proj -> flash attention (8 heads) -> out proj
// ---------------------------------------------------------------------------
extern "C" void kernel_launch(void* const* d_in, const int* in_sizes, int n_in,
                              void* d_out, int out_size)
{
    const float* query = (const float*)d_in[0];   // [1,4096,512]
    const float* w_in  = (const float*)d_in[1];   // [1536,512]
    const float* b_in  = (const float*)d_in[2];   // [1536]
    const float* w_out = (const float*)d_in[3];   // [512,512]
    const float* b_out = (const float*)d_in[4];   // [512]
    float*       out   = (float*)d_out;           // [1,4096,512]

    float *qkv, *attn;
    cudaGetSymbolAddress((void**)&qkv,  g_qkv);
    cudaGetSymbolAddress((void**)&attn, g_attn);

    // 1) QKV projection: [4096,512] @ [1536,512]^T + bias -> [4096,1536]
    {
        dim3 grid(LDQKV / 128, S_LEN / 128);  // (12, 32)
        gemm_bias_kernel<<<grid, 256>>>(query, w_in, b_in, qkv,
                                        S_LEN, LDQKV, D_MODEL);
    }

    // 2) Flash attention per head
    {
        cudaFuncSetAttribute(flash_attn_kernel,
                             cudaFuncAttributeMaxDynamicSharedMemorySize,
                             FLASH_SMEM);
        dim3 grid(S_LEN / 64, H_NUM);  // (64, 8)
        flash_attn_kernel<<<grid, 256, FLASH_SMEM>>>(qkv, attn);
    }

    // 3) Output projection: [4096,512] @ [512,512]^T + bias -> [4096,512]
    {
        dim3 grid(D_MODEL / 128, S_LEN / 128);  // (4, 32)
        gemm_bias_kernel<<<grid, 256>>>(attn, w_out, b_out, out,
                                        S_LEN, D_MODEL, D_MODEL);
    }
}

// round 2
// speedup vs baseline: 2.4660x; 2.4660x over previous
#include <cuda_runtime.h>
#include <math_constants.h>
#include <cstdint>

// Problem constants
#define S_LEN   4096
#define D_MODEL 512
#define H_NUM   8
#define HD      64
#define LDQKV   1536      // 3*D_MODEL

// Scratch (no cudaMalloc allowed)
__device__ float g_qkv[S_LEN * LDQKV];    // [4096,1536]  Q|K|V
__device__ float g_attn[S_LEN * D_MODEL]; // [4096,512]   attention output (head-merged)

// ---------------------------------------------------------------------------
// Helpers: tf32 round + m16n8k8 tf32 mma
// ---------------------------------------------------------------------------
__device__ __forceinline__ uint32_t f2tf32(float x) {
    uint32_t r;
    asm("cvt.rna.tf32.f32 %0, %1;" : "=r"(r) : "f"(x));
    return r;
}

__device__ __forceinline__ void mma_tf32(float d[4], const uint32_t a[4],
                                         const uint32_t b[2], const float c[4]) {
    asm volatile(
        "mma.sync.aligned.m16n8k8.row.col.f32.tf32.tf32.f32 "
        "{%0,%1,%2,%3}, {%4,%5,%6,%7}, {%8,%9}, {%10,%11,%12,%13};"
        : "=f"(d[0]), "=f"(d[1]), "=f"(d[2]), "=f"(d[3])
        : "r"(a[0]), "r"(a[1]), "r"(a[2]), "r"(a[3]),
          "r"(b[0]), "r"(b[1]),
          "f"(c[0]), "f"(c[1]), "f"(c[2]), "f"(c[3]));
}

// ---------------------------------------------------------------------------
// GEMM: C[M,N] = A[M,K] @ B[N,K]^T + bias[N]  (SIMT fp32, unchanged from R0)
// ---------------------------------------------------------------------------
__global__ __launch_bounds__(256) void gemm_bias_kernel(
    const float* __restrict__ A, const float* __restrict__ B,
    const float* __restrict__ bias, float* __restrict__ C,
    int M, int N, int K)
{
    __shared__ float As[16][132];
    __shared__ float Bs[16][132];

    const int tid = threadIdx.x;
    const int tx  = tid & 15;
    const int ty  = tid >> 4;
    const int m0  = blockIdx.y * 128;
    const int n0  = blockIdx.x * 128;

    float acc[8][8];
#pragma unroll
    for (int i = 0; i < 8; i++)
#pragma unroll
        for (int j = 0; j < 8; j++) acc[i][j] = 0.0f;

    for (int k0 = 0; k0 < K; k0 += 16) {
#pragma unroll
        for (int i = 0; i < 2; i++) {
            int f   = tid + i * 256;
            int row = f >> 2;
            int kq  = (f & 3) << 2;
            float4 a = *(const float4*)(A + (size_t)(m0 + row) * K + k0 + kq);
            As[kq + 0][row] = a.x; As[kq + 1][row] = a.y;
            As[kq + 2][row] = a.z; As[kq + 3][row] = a.w;
            float4 b = *(const float4*)(B + (size_t)(n0 + row) * K + k0 + kq);
            Bs[kq + 0][row] = b.x; Bs[kq + 1][row] = b.y;
            Bs[kq + 2][row] = b.z; Bs[kq + 3][row] = b.w;
        }
        __syncthreads();

#pragma unroll
        for (int kk = 0; kk < 16; kk++) {
            float ra[8], rb[8];
            *(float4*)&ra[0] = *(const float4*)&As[kk][ty * 4];
            *(float4*)&ra[4] = *(const float4*)&As[kk][64 + ty * 4];
            *(float4*)&rb[0] = *(const float4*)&Bs[kk][tx * 4];
            *(float4*)&rb[4] = *(const float4*)&Bs[kk][64 + tx * 4];
#pragma unroll
            for (int i = 0; i < 8; i++)
#pragma unroll
                for (int j = 0; j < 8; j++)
                    acc[i][j] = fmaf(ra[i], rb[j], acc[i][j]);
        }
        __syncthreads();
    }

#pragma unroll
    for (int ih = 0; ih < 2; ih++)
#pragma unroll
        for (int r = 0; r < 4; r++) {
            int row = m0 + ih * 64 + ty * 4 + r;
#pragma unroll
            for (int jh = 0; jh < 2; jh++) {
                int col = n0 + jh * 64 + tx * 4;
                float4 bv = *(const float4*)(bias + col);
                float4 o;
                o.x = acc[ih * 4 + r][jh * 4 + 0] + bv.x;
                o.y = acc[ih * 4 + r][jh * 4 + 1] + bv.y;
                o.z = acc[ih * 4 + r][jh * 4 + 2] + bv.z;
                o.w = acc[ih * 4 + r][jh * 4 + 3] + bv.w;
                *(float4*)(C + (size_t)row * N + col) = o;
            }
        }
}

// ---------------------------------------------------------------------------
// Flash attention with tf32 tensor-core mma (m16n8k8), FA2 style.
// Br=Bc=64, Hd=64, 4 warps/CTA; each warp owns 16 q-rows.
// Q fragments persist in registers; K/V staged per tile (tf32-rounded).
// Smem pads: LDA=68 for Qs/Ks/Ps (bank==lane, conflict-free for A- and
// Kt-B-frag patterns), LDB=72 for Vs (8k+n pattern, conflict-free).
// ---------------------------------------------------------------------------
#define LDA 68
#define LDB 72
#define FLASH_SMEM ((64 * LDA * 2 + 64 * LDB) * 4)   // Ks + Ps + Vs = 53248 B

__global__ void __launch_bounds__(128) flash_mma_kernel(
    const float* __restrict__ qkv, float* __restrict__ attn_out)
{
    extern __shared__ float sm[];
    float* Ks = sm;                        // [64][LDA] (also Q staging)
    float* Vs = sm + 64 * LDA;             // [64][LDB]
    float* Ps = sm + 64 * LDA + 64 * LDB;  // [64][LDA]

    const int tid  = threadIdx.x;
    const int lane = tid & 31;
    const int wid  = tid >> 5;
    const int qc   = lane & 3;        // thread-in-quad
    const int qg   = lane >> 2;       // quad/group id 0..7
    const int h    = blockIdx.y;
    const int q0   = blockIdx.x * 64;
    const int colb = h * HD;

    const int r0 = wid * 16 + qg;     // local row (0..63)
    const int r1 = r0 + 8;

    // ---- Stage Q (scaled by 1/sqrt(64), tf32-rounded) into Ks buffer ----
#pragma unroll
    for (int i = 0; i < 8; i++) {
        int f   = tid + i * 128;            // 0..1023 float4 idx
        int row = f >> 4;
        int c4  = (f & 15) << 2;
        float4 a = *(const float4*)(qkv + (size_t)(q0 + row) * LDQKV + colb + c4);
        a.x = __uint_as_float(f2tf32(a.x * 0.125f));
        a.y = __uint_as_float(f2tf32(a.y * 0.125f));
        a.z = __uint_as_float(f2tf32(a.z * 0.125f));
        a.w = __uint_as_float(f2tf32(a.w * 0.125f));
        *(float4*)(Ks + row * LDA + c4) = a;
    }
    __syncthreads();

    // ---- Q fragments into registers: 8 k-chunks of m16k8 ----
    uint32_t qf[8][4];
#pragma unroll
    for (int kc = 0; kc < 8; kc++) {
        int d0 = kc * 8;
        qf[kc][0] = __float_as_uint(Ks[r0 * LDA + d0 + qc]);
        qf[kc][1] = __float_as_uint(Ks[r1 * LDA + d0 + qc]);
        qf[kc][2] = __float_as_uint(Ks[r0 * LDA + d0 + qc + 4]);
        qf[kc][3] = __float_as_uint(Ks[r1 * LDA + d0 + qc + 4]);
    }

    float o[8][4];
#pragma unroll
    for (int nt = 0; nt < 8; nt++)
#pragma unroll
        for (int j = 0; j < 4; j++) o[nt][j] = 0.0f;
    float m_lo = -CUDART_INF_F, m_hi = -CUDART_INF_F;
    float l_lo = 0.0f, l_hi = 0.0f;

    for (int k0 = 0; k0 < S_LEN; k0 += 64) {
        __syncthreads();   // all warps done reading Qs/Ks/Vs from prev phase
        // ---- Stage K, V tiles (tf32-rounded) ----
#pragma unroll
        for (int i = 0; i < 8; i++) {
            int f   = tid + i * 128;
            int row = f >> 4;
            int c4  = (f & 15) << 2;
            const float* base = qkv + (size_t)(k0 + row) * LDQKV + colb + c4;
            float4 kv = *(const float4*)(base + D_MODEL);
            kv.x = __uint_as_float(f2tf32(kv.x));
            kv.y = __uint_as_float(f2tf32(kv.y));
            kv.z = __uint_as_float(f2tf32(kv.z));
            kv.w = __uint_as_float(f2tf32(kv.w));
            *(float4*)(Ks + row * LDA + c4) = kv;
            float4 vv = *(const float4*)(base + 2 * D_MODEL);
            vv.x = __uint_as_float(f2tf32(vv.x));
            vv.y = __uint_as_float(f2tf32(vv.y));
            vv.z = __uint_as_float(f2tf32(vv.z));
            vv.w = __uint_as_float(f2tf32(vv.w));
            *(float4*)(Vs + row * LDB + c4) = vv;
        }
        __syncthreads();

        // ---- S = Q K^T (scale pre-folded into Q) ----
        float s[8][4];
#pragma unroll
        for (int nt = 0; nt < 8; nt++)
#pragma unroll
            for (int j = 0; j < 4; j++) s[nt][j] = 0.0f;

#pragma unroll
        for (int kc = 0; kc < 8; kc++) {
#pragma unroll
            for (int nt = 0; nt < 8; nt++) {
                const float* kb = Ks + (nt * 8 + qg) * LDA + kc * 8 + qc;
                uint32_t b[2];
                b[0] = __float_as_uint(kb[0]);
                b[1] = __float_as_uint(kb[4]);
                mma_tf32(s[nt], qf[kc], b, s[nt]);
            }
        }

        // ---- Online softmax (rows r0, r1) ----
        float mlo = -CUDART_INF_F, mhi = -CUDART_INF_F;
#pragma unroll
        for (int nt = 0; nt < 8; nt++) {
            mlo = fmaxf(mlo, fmaxf(s[nt][0], s[nt][1]));
            mhi = fmaxf(mhi, fmaxf(s[nt][2], s[nt][3]));
        }
        mlo = fmaxf(mlo, __shfl_xor_sync(0xffffffffu, mlo, 1));
        mlo = fmaxf(mlo, __shfl_xor_sync(0xffffffffu, mlo, 2));
        mhi = fmaxf(mhi, __shfl_xor_sync(0xffffffffu, mhi, 1));
        mhi = fmaxf(mhi, __shfl_xor_sync(0xffffffffu, mhi, 2));

        float mnlo = fmaxf(m_lo, mlo);
        float mnhi = fmaxf(m_hi, mhi);
        float alo  = __expf(m_lo - mnlo);   // 0 on first tile
        float ahi  = __expf(m_hi - mnhi);
        m_lo = mnlo; m_hi = mnhi;

        float tlo = 0.0f, thi = 0.0f;
#pragma unroll
        for (int nt = 0; nt < 8; nt++) {
            float p0 = __expf(s[nt][0] - mnlo);
            float p1 = __expf(s[nt][1] - mnlo);
            float p2 = __expf(s[nt][2] - mnhi);
            float p3 = __expf(s[nt][3] - mnhi);
            tlo += p0 + p1;
            thi += p2 + p3;
            uint2 plo = make_uint2(f2tf32(p0), f2tf32(p1));
            uint2 phi = make_uint2(f2tf32(p2), f2tf32(p3));
            *(uint2*)(Ps + r0 * LDA + nt * 8 + 2 * qc) = plo;
            *(uint2*)(Ps + r1 * LDA + nt * 8 + 2 * qc) = phi;
        }
        tlo += __shfl_xor_sync(0xffffffffu, tlo, 1);
        tlo += __shfl_xor_sync(0xffffffffu, tlo, 2);
        thi += __shfl_xor_sync(0xffffffffu, thi, 1);
        thi += __shfl_xor_sync(0xffffffffu, thi, 2);
        l_lo = l_lo * alo + tlo;
        l_hi = l_hi * ahi + thi;

#pragma unroll
        for (int nt = 0; nt < 8; nt++) {
            o[nt][0] *= alo; o[nt][1] *= alo;
            o[nt][2] *= ahi; o[nt][3] *= ahi;
        }

        __syncwarp();   // P rows are warp-private; order STS before LDS

        // ---- O += P V ----
#pragma unroll
        for (int kc = 0; kc < 8; kc++) {
            uint32_t a[4];
            a[0] = __float_as_uint(Ps[r0 * LDA + kc * 8 + qc]);
            a[1] = __float_as_uint(Ps[r1 * LDA + kc * 8 + qc]);
            a[2] = __float_as_uint(Ps[r0 * LDA + kc * 8 + qc + 4]);
            a[3] = __float_as_uint(Ps[r1 * LDA + kc * 8 + qc + 4]);
#pragma unroll
            for (int nt = 0; nt < 8; nt++) {
                uint32_t b[2];
                b[0] = __float_as_uint(Vs[(kc * 8 + qc) * LDB + nt * 8 + qg]);
                b[1] = __float_as_uint(Vs[(kc * 8 + qc + 4) * LDB + nt * 8 + qg]);
                mma_tf32(o[nt], a, b, o[nt]);
            }
        }
    }

    // ---- Epilogue: normalize, write out ----
    float ilo = 1.0f / l_lo;
    float ihi = 1.0f / l_hi;
#pragma unroll
    for (int nt = 0; nt < 8; nt++) {
        float2 vlo = make_float2(o[nt][0] * ilo, o[nt][1] * ilo);
        float2 vhi = make_float2(o[nt][2] * ihi, o[nt][3] * ihi);
        *(float2*)(attn_out + (size_t)(q0 + r0) * D_MODEL + colb + nt * 8 + 2 * qc) = vlo;
        *(float2*)(attn_out + (size_t)(q0 + r1) * D_MODEL + colb + nt * 8 + 2 * qc) = vhi;
    }
}

// ---------------------------------------------------------------------------
// Launch: QKV proj -> flash attention (tf32 mma) -> out proj
// ---------------------------------------------------------------------------
extern "C" void kernel_launch(void* const* d_in, const int* in_sizes, int n_in,
                              void* d_out, int out_size)
{
    const float* query = (const float*)d_in[0];   // [1,4096,512]
    const float* w_in  = (const float*)d_in[1];   // [1536,512]
    const float* b_in  = (const float*)d_in[2];   // [1536]
    const float* w_out = (const float*)d_in[3];   // [512,512]
    const float* b_out = (const float*)d_in[4];   // [512]
    float*       out   = (float*)d_out;           // [1,4096,512]

    float *qkv, *attn;
    cudaGetSymbolAddress((void**)&qkv,  g_qkv);
    cudaGetSymbolAddress((void**)&attn, g_attn);

    // 1) QKV projection: [4096,512] @ [1536,512]^T + bias -> [4096,1536]
    {
        dim3 grid(LDQKV / 128, S_LEN / 128);
        gemm_bias_kernel<<<grid, 256>>>(query, w_in, b_in, qkv,
                                        S_LEN, LDQKV, D_MODEL);
    }

    // 2) Flash attention per head (tf32 tensor cores)
    {
        cudaFuncSetAttribute(flash_mma_kernel,
                             cudaFuncAttributeMaxDynamicSharedMemorySize,
                             FLASH_SMEM);
        dim3 grid(S_LEN / 64, H_NUM);
        flash_mma_kernel<<<grid, 128, FLASH_SMEM>>>(qkv, attn);
    }

    // 3) Output projection: [4096,512] @ [512,512]^T + bias -> [4096,512]
    {
        dim3 grid(D_MODEL / 128, S_LEN / 128);
        gemm_bias_kernel<<<grid, 256>>>(attn, w_out, b_out, out,
                                        S_LEN, D_MODEL, D_MODEL);
    }
}

// round 3
// speedup vs baseline: 3.0073x; 1.2195x over previous
#include <cuda_runtime.h>
#include <math_constants.h>
#include <cstdint>

// Problem constants
#define S_LEN   4096
#define D_MODEL 512
#define H_NUM   8
#define HD      64
#define LDQKV   1536      // 3*D_MODEL

// Scratch (no cudaMalloc allowed)
__device__ float g_qkv[S_LEN * LDQKV];    // [4096,1536]  Q|K|V
__device__ float g_attn[S_LEN * D_MODEL]; // [4096,512]   attention output (head-merged)

// ---------------------------------------------------------------------------
// Helpers: tf32 round + m16n8k8 tf32 mma
// ---------------------------------------------------------------------------
__device__ __forceinline__ uint32_t f2tf32(float x) {
    uint32_t r;
    asm("cvt.rna.tf32.f32 %0, %1;" : "=r"(r) : "f"(x));
    return r;
}

__device__ __forceinline__ void mma_tf32(float d[4], const uint32_t a[4],
                                         const uint32_t b[2], const float c[4]) {
    asm volatile(
        "mma.sync.aligned.m16n8k8.row.col.f32.tf32.tf32.f32 "
        "{%0,%1,%2,%3}, {%4,%5,%6,%7}, {%8,%9}, {%10,%11,%12,%13};"
        : "=f"(d[0]), "=f"(d[1]), "=f"(d[2]), "=f"(d[3])
        : "r"(a[0]), "r"(a[1]), "r"(a[2]), "r"(a[3]),
          "r"(b[0]), "r"(b[1]),
          "f"(c[0]), "f"(c[1]), "f"(c[2]), "f"(c[3]));
}

// ---------------------------------------------------------------------------
// tf32 tensor-core GEMM: C[M,N] = A[M,K] @ B[N,K]^T + bias[N]
// 128x128 CTA tile, BK=32, 256 threads = 8 warps as 4(m)x2(n), warp tile
// 32x64. Double-buffered smem with register prefetch; one sync per K-tile.
// Smem pad 36: fragment LDS bank = (4*qg + 8*kc + qc) mod 32 -> conflict-free.
// Requires M%128==0, N%128==0, K%32==0.
// ---------------------------------------------------------------------------
#define GLD 36
#define GEMM_SMEM (2 * 2 * 128 * GLD * 4)   // 73728 bytes

__global__ void __launch_bounds__(256) gemm_tf32_bias(
    const float* __restrict__ A, const float* __restrict__ B,
    const float* __restrict__ bias, float* __restrict__ C,
    int M, int N, int K)
{
    extern __shared__ float sm[];
    // As[buf][row][k], Bs[buf][n][k]
    float* As[2] = { sm,                sm + 128 * GLD     };
    float* Bs[2] = { sm + 2 * 128 * GLD, sm + 3 * 128 * GLD };

    const int tid  = threadIdx.x;
    const int lane = tid & 31;
    const int wid  = tid >> 5;
    const int qc   = lane & 3;
    const int qg   = lane >> 2;
    const int wm   = (wid & 3) * 32;   // warp m offset in tile
    const int wn   = (wid >> 2) * 64;  // warp n offset in tile
    const int m0   = blockIdx.y * 128;
    const int n0   = blockIdx.x * 128;

    float acc[2][8][4];
#pragma unroll
    for (int mf = 0; mf < 2; mf++)
#pragma unroll
        for (int nf = 0; nf < 8; nf++)
#pragma unroll
            for (int j = 0; j < 4; j++) acc[mf][nf][j] = 0.0f;

    const int nt = K / 32;    // number of K-tiles

    float4 pa[4], pb[4];
    // prefetch tile 0 into registers
#pragma unroll
    for (int i = 0; i < 4; i++) {
        int f   = tid + i * 256;     // 0..1023
        int row = f >> 3;
        int c4  = (f & 7) << 2;
        pa[i] = *(const float4*)(A + (size_t)(m0 + row) * K + c4);
        pb[i] = *(const float4*)(B + (size_t)(n0 + row) * K + c4);
    }
    // stage tile 0 (tf32-rounded)
#pragma unroll
    for (int i = 0; i < 4; i++) {
        int f   = tid + i * 256;
        int row = f >> 3;
        int c4  = (f & 7) << 2;
        float* a = As[0] + row * GLD + c4;
        a[0] = __uint_as_float(f2tf32(pa[i].x));
        a[1] = __uint_as_float(f2tf32(pa[i].y));
        a[2] = __uint_as_float(f2tf32(pa[i].z));
        a[3] = __uint_as_float(f2tf32(pa[i].w));
        float* b = Bs[0] + row * GLD + c4;
        b[0] = __uint_as_float(f2tf32(pb[i].x));
        b[1] = __uint_as_float(f2tf32(pb[i].y));
        b[2] = __uint_as_float(f2tf32(pb[i].z));
        b[3] = __uint_as_float(f2tf32(pb[i].w));
    }
    __syncthreads();

    for (int t = 0; t < nt; t++) {
        const int cur = t & 1;
        // prefetch next tile from gmem
        if (t + 1 < nt) {
            int k0 = (t + 1) * 32;
#pragma unroll
            for (int i = 0; i < 4; i++) {
                int f   = tid + i * 256;
                int row = f >> 3;
                int c4  = (f & 7) << 2;
                pa[i] = *(const float4*)(A + (size_t)(m0 + row) * K + k0 + c4);
                pb[i] = *(const float4*)(B + (size_t)(n0 + row) * K + k0 + c4);
            }
        }

        // compute on current buffer
        const float* as = As[cur];
        const float* bs = Bs[cur];
#pragma unroll
        for (int kc = 0; kc < 4; kc++) {
            uint32_t bfr[8][2];
#pragma unroll
            for (int nf = 0; nf < 8; nf++) {
                const float* bp = bs + (wn + nf * 8 + qg) * GLD + kc * 8 + qc;
                bfr[nf][0] = __float_as_uint(bp[0]);
                bfr[nf][1] = __float_as_uint(bp[4]);
            }
#pragma unroll
            for (int mf = 0; mf < 2; mf++) {
                const float* ap = as + (wm + mf * 16 + qg) * GLD + kc * 8 + qc;
                uint32_t afr[4];
                afr[0] = __float_as_uint(ap[0]);
                afr[1] = __float_as_uint(ap[8 * GLD]);
                afr[2] = __float_as_uint(ap[4]);
                afr[3] = __float_as_uint(ap[8 * GLD + 4]);
#pragma unroll
                for (int nf = 0; nf < 8; nf++)
                    mma_tf32(acc[mf][nf], afr, bfr[nf], acc[mf][nf]);
            }
        }

        // stage next tile
        if (t + 1 < nt) {
            const int nxt = cur ^ 1;
#pragma unroll
            for (int i = 0; i < 4; i++) {
                int f   = tid + i * 256;
                int row = f >> 3;
                int c4  = (f & 7) << 2;
                float* a = As[nxt] + row * GLD + c4;
                a[0] = __uint_as_float(f2tf32(pa[i].x));
                a[1] = __uint_as_float(f2tf32(pa[i].y));
                a[2] = __uint_as_float(f2tf32(pa[i].z));
                a[3] = __uint_as_float(f2tf32(pa[i].w));
                float* b = Bs[nxt] + row * GLD + c4;
                b[0] = __uint_as_float(f2tf32(pb[i].x));
                b[1] = __uint_as_float(f2tf32(pb[i].y));
                b[2] = __uint_as_float(f2tf32(pb[i].z));
                b[3] = __uint_as_float(f2tf32(pb[i].w));
            }
            __syncthreads();
        }
    }

    // epilogue: add bias, store
#pragma unroll
    for (int mf = 0; mf < 2; mf++) {
        int row0 = m0 + wm + mf * 16 + qg;
#pragma unroll
        for (int nf = 0; nf < 8; nf++) {
            int col = n0 + wn + nf * 8 + 2 * qc;
            float b0 = bias[col], b1 = bias[col + 1];
            float2 v0 = make_float2(acc[mf][nf][0] + b0, acc[mf][nf][1] + b1);
            float2 v1 = make_float2(acc[mf][nf][2] + b0, acc[mf][nf][3] + b1);
            *(float2*)(C + (size_t)row0 * N + col)       = v0;
            *(float2*)(C + (size_t)(row0 + 8) * N + col) = v1;
        }
    }
}

// ---------------------------------------------------------------------------
// Flash attention with tf32 tensor-core mma (m16n8k8), FA2 style (R1, passing).
// ---------------------------------------------------------------------------
#define LDA 68
#define LDB 72
#define FLASH_SMEM ((64 * LDA * 2 + 64 * LDB) * 4)   // Ks + Ps + Vs = 53248 B

__global__ void __launch_bounds__(128) flash_mma_kernel(
    const float* __restrict__ qkv, float* __restrict__ attn_out)
{
    extern __shared__ float sm[];
    float* Ks = sm;                        // [64][LDA] (also Q staging)
    float* Vs = sm + 64 * LDA;             // [64][LDB]
    float* Ps = sm + 64 * LDA + 64 * LDB;  // [64][LDA]

    const int tid  = threadIdx.x;
    const int lane = tid & 31;
    const int wid  = tid >> 5;
    const int qc   = lane & 3;
    const int qg   = lane >> 2;
    const int h    = blockIdx.y;
    const int q0   = blockIdx.x * 64;
    const int colb = h * HD;

    const int r0 = wid * 16 + qg;
    const int r1 = r0 + 8;

    // ---- Stage Q (scaled, tf32-rounded) ----
#pragma unroll
    for (int i = 0; i < 8; i++) {
        int f   = tid + i * 128;
        int row = f >> 4;
        int c4  = (f & 15) << 2;
        float4 a = *(const float4*)(qkv + (size_t)(q0 + row) * LDQKV + colb + c4);
        a.x = __uint_as_float(f2tf32(a.x * 0.125f));
        a.y = __uint_as_float(f2tf32(a.y * 0.125f));
        a.z = __uint_as_float(f2tf32(a.z * 0.125f));
        a.w = __uint_as_float(f2tf32(a.w * 0.125f));
        *(float4*)(Ks + row * LDA + c4) = a;
    }
    __syncthreads();

    uint32_t qf[8][4];
#pragma unroll
    for (int kc = 0; kc < 8; kc++) {
        int d0 = kc * 8;
        qf[kc][0] = __float_as_uint(Ks[r0 * LDA + d0 + qc]);
        qf[kc][1] = __float_as_uint(Ks[r1 * LDA + d0 + qc]);
        qf[kc][2] = __float_as_uint(Ks[r0 * LDA + d0 + qc + 4]);
        qf[kc][3] = __float_as_uint(Ks[r1 * LDA + d0 + qc + 4]);
    }

    float o[8][4];
#pragma unroll
    for (int nt = 0; nt < 8; nt++)
#pragma unroll
        for (int j = 0; j < 4; j++) o[nt][j] = 0.0f;
    float m_lo = -CUDART_INF_F, m_hi = -CUDART_INF_F;
    float l_lo = 0.0f, l_hi = 0.0f;

    for (int k0 = 0; k0 < S_LEN; k0 += 64) {
        __syncthreads();
#pragma unroll
        for (int i = 0; i < 8; i++) {
            int f   = tid + i * 128;
            int row = f >> 4;
            int c4  = (f & 15) << 2;
            const float* base = qkv + (size_t)(k0 + row) * LDQKV + colb + c4;
            float4 kv = *(const float4*)(base + D_MODEL);
            kv.x = __uint_as_float(f2tf32(kv.x));
            kv.y = __uint_as_float(f2tf32(kv.y));
            kv.z = __uint_as_float(f2tf32(kv.z));
            kv.w = __uint_as_float(f2tf32(kv.w));
            *(float4*)(Ks + row * LDA + c4) = kv;
            float4 vv = *(const float4*)(base + 2 * D_MODEL);
            vv.x = __uint_as_float(f2tf32(vv.x));
            vv.y = __uint_as_float(f2tf32(vv.y));
            vv.z = __uint_as_float(f2tf32(vv.z));
            vv.w = __uint_as_float(f2tf32(vv.w));
            *(float4*)(Vs + row * LDB + c4) = vv;
        }
        __syncthreads();

        float s[8][4];
#pragma unroll
        for (int nt = 0; nt < 8; nt++)
#pragma unroll
            for (int j = 0; j < 4; j++) s[nt][j] = 0.0f;

#pragma unroll
        for (int kc = 0; kc < 8; kc++) {
#pragma unroll
            for (int nt = 0; nt < 8; nt++) {
                const float* kb = Ks + (nt * 8 + qg) * LDA + kc * 8 + qc;
                uint32_t b[2];
                b[0] = __float_as_uint(kb[0]);
                b[1] = __float_as_uint(kb[4]);
                mma_tf32(s[nt], qf[kc], b, s[nt]);
            }
        }

        float mlo = -CUDART_INF_F, mhi = -CUDART_INF_F;
#pragma unroll
        for (int nt = 0; nt < 8; nt++) {
            mlo = fmaxf(mlo, fmaxf(s[nt][0], s[nt][1]));
            mhi = fmaxf(mhi, fmaxf(s[nt][2], s[nt][3]));
        }
        mlo = fmaxf(mlo, __shfl_xor_sync(0xffffffffu, mlo, 1));
        mlo = fmaxf(mlo, __shfl_xor_sync(0xffffffffu, mlo, 2));
        mhi = fmaxf(mhi, __shfl_xor_sync(0xffffffffu, mhi, 1));
        mhi = fmaxf(mhi, __shfl_xor_sync(0xffffffffu, mhi, 2));

        float mnlo = fmaxf(m_lo, mlo);
        float mnhi = fmaxf(m_hi, mhi);
        float alo  = __expf(m_lo - mnlo);
        float ahi  = __expf(m_hi - mnhi);
        m_lo = mnlo; m_hi = mnhi;

        float tlo = 0.0f, thi = 0.0f;
#pragma unroll
        for (int nt = 0; nt < 8; nt++) {
            float p0 = __expf(s[nt][0] - mnlo);
            float p1 = __expf(s[nt][1] - mnlo);
            float p2 = __expf(s[nt][2] - mnhi);
            float p3 = __expf(s[nt][3] - mnhi);
            tlo += p0 + p1;
            thi += p2 + p3;
            uint2 plo = make_uint2(f2tf32(p0), f2tf32(p1));
            uint2 phi = make_uint2(f2tf32(p2), f2tf32(p3));
            *(uint2*)(Ps + r0 * LDA + nt * 8 + 2 * qc) = plo;
            *(uint2*)(Ps + r1 * LDA + nt * 8 + 2 * qc) = phi;
        }
        tlo += __shfl_xor_sync(0xffffffffu, tlo, 1);
        tlo += __shfl_xor_sync(0xffffffffu, tlo, 2);
        thi += __shfl_xor_sync(0xffffffffu, thi, 1);
        thi += __shfl_xor_sync(0xffffffffu, thi, 2);
        l_lo = l_lo * alo + tlo;
        l_hi = l_hi * ahi + thi;

#pragma unroll
        for (int nt = 0; nt < 8; nt++) {
            o[nt][0] *= alo; o[nt][1] *= alo;
            o[nt][2] *= ahi; o[nt][3] *= ahi;
        }

        __syncwarp();

#pragma unroll
        for (int kc = 0; kc < 8; kc++) {
            uint32_t a[4];
            a[0] = __float_as_uint(Ps[r0 * LDA + kc * 8 + qc]);
            a[1] = __float_as_uint(Ps[r1 * LDA + kc * 8 + qc]);
            a[2] = __float_as_uint(Ps[r0 * LDA + kc * 8 + qc + 4]);
            a[3] = __float_as_uint(Ps[r1 * LDA + kc * 8 + qc + 4]);
#pragma unroll
            for (int nt = 0; nt < 8; nt++) {
                uint32_t b[2];
                b[0] = __float_as_uint(Vs[(kc * 8 + qc) * LDB + nt * 8 + qg]);
                b[1] = __float_as_uint(Vs[(kc * 8 + qc + 4) * LDB + nt * 8 + qg]);
                mma_tf32(o[nt], a, b, o[nt]);
            }
        }
    }

    float ilo = 1.0f / l_lo;
    float ihi = 1.0f / l_hi;
#pragma unroll
    for (int nt = 0; nt < 8; nt++) {
        float2 vlo = make_float2(o[nt][0] * ilo, o[nt][1] * ilo);
        float2 vhi = make_float2(o[nt][2] * ihi, o[nt][3] * ihi);
        *(float2*)(attn_out + (size_t)(q0 + r0) * D_MODEL + colb + nt * 8 + 2 * qc) = vlo;
        *(float2*)(attn_out + (size_t)(q0 + r1) * D_MODEL + colb + nt * 8 + 2 * qc) = vhi;
    }
}

// ---------------------------------------------------------------------------
// Launch: QKV proj (tf32 mma) -> flash attention (tf32 mma) -> out proj
// ---------------------------------------------------------------------------
extern "C" void kernel_launch(void* const* d_in, const int* in_sizes, int n_in,
                              void* d_out, int out_size)
{
    const float* query = (const float*)d_in[0];   // [1,4096,512]
    const float* w_in  = (const float*)d_in[1];   // [1536,512]
    const float* b_in  = (const float*)d_in[2];   // [1536]
    const float* w_out = (const float*)d_in[3];   // [512,512]
    const float* b_out = (const float*)d_in[4];   // [512]
    float*       out   = (float*)d_out;           // [1,4096,512]

    float *qkv, *attn;
    cudaGetSymbolAddress((void**)&qkv,  g_qkv);
    cudaGetSymbolAddress((void**)&attn, g_attn);

    cudaFuncSetAttribute(gemm_tf32_bias,
                         cudaFuncAttributeMaxDynamicSharedMemorySize, GEMM_SMEM);

    // 1) QKV projection: [4096,512] @ [1536,512]^T + bias -> [4096,1536]
    {
        dim3 grid(LDQKV / 128, S_LEN / 128);   // (12, 32)
        gemm_tf32_bias<<<grid, 256, GEMM_SMEM>>>(query, w_in, b_in, qkv,
                                                 S_LEN, LDQKV, D_MODEL);
    }

    // 2) Flash attention per head (tf32 tensor cores)
    {
        cudaFuncSetAttribute(flash_mma_kernel,
                             cudaFuncAttributeMaxDynamicSharedMemorySize,
                             FLASH_SMEM);
        dim3 grid(S_LEN / 64, H_NUM);
        flash_mma_kernel<<<grid, 128, FLASH_SMEM>>>(qkv, attn);
    }

    // 3) Output projection: [4096,512] @ [512,512]^T + bias -> [4096,512]
    {
        dim3 grid(D_MODEL / 128, S_LEN / 128);  // (4, 32)
        gemm_tf32_bias<<<grid, 256, GEMM_SMEM>>>(attn, w_out, b_out, out,
                                                 S_LEN, D_MODEL, D_MODEL);
    }
}

// round 4
// speedup vs baseline: 3.4187x; 1.1368x over previous
#include <cuda_runtime.h>
#include <math_constants.h>
#include <cstdint>

// Problem constants
#define S_LEN   4096
#define D_MODEL 512
#define H_NUM   8
#define HD      64
#define LDQKV   1536      // 3*D_MODEL

// Scratch (no cudaMalloc allowed)
__device__ float g_qkv[S_LEN * LDQKV];    // [4096,1536]  Q|K|V
__device__ float g_attn[S_LEN * D_MODEL]; // [4096,512]   attention output (head-merged)

// ---------------------------------------------------------------------------
// Helpers: tf32 round + m16n8k8 tf32 mma
// ---------------------------------------------------------------------------
__device__ __forceinline__ uint32_t f2tf32(float x) {
    uint32_t r;
    asm("cvt.rna.tf32.f32 %0, %1;" : "=r"(r) : "f"(x));
    return r;
}

__device__ __forceinline__ void mma_tf32(float d[4], const uint32_t a[4],
                                         const uint32_t b[2], const float c[4]) {
    asm volatile(
        "mma.sync.aligned.m16n8k8.row.col.f32.tf32.tf32.f32 "
        "{%0,%1,%2,%3}, {%4,%5,%6,%7}, {%8,%9}, {%10,%11,%12,%13};"
        : "=f"(d[0]), "=f"(d[1]), "=f"(d[2]), "=f"(d[3])
        : "r"(a[0]), "r"(a[1]), "r"(a[2]), "r"(a[3]),
          "r"(b[0]), "r"(b[1]),
          "f"(c[0]), "f"(c[1]), "f"(c[2]), "f"(c[3]));
}

// ---------------------------------------------------------------------------
// tf32 tensor-core GEMM: C[M,N] = A[M,K] @ B[N,K]^T + bias[N]
// 128x128 CTA tile, BK=32, 256 threads = 8 warps (4m x 2n), warp tile 32x64.
// Double-buffered smem with register prefetch. min-blocks=2 caps regs at 128
// so two CTAs co-reside per SM (R2 was reg-limited to one -> issue 26.7%).
// ---------------------------------------------------------------------------
#define GLD 36
#define GEMM_SMEM (2 * 2 * 128 * GLD * 4)   // 73728 bytes

__global__ void __launch_bounds__(256, 2) gemm_tf32_bias(
    const float* __restrict__ A, const float* __restrict__ B,
    const float* __restrict__ bias, float* __restrict__ C,
    int M, int N, int K)
{
    extern __shared__ float sm[];
    float* As[2] = { sm,                 sm + 128 * GLD     };
    float* Bs[2] = { sm + 2 * 128 * GLD, sm + 3 * 128 * GLD };

    const int tid  = threadIdx.x;
    const int lane = tid & 31;
    const int wid  = tid >> 5;
    const int qc   = lane & 3;
    const int qg   = lane >> 2;
    const int wm   = (wid & 3) * 32;
    const int wn   = (wid >> 2) * 64;
    const int m0   = blockIdx.y * 128;
    const int n0   = blockIdx.x * 128;

    float acc[2][8][4];
#pragma unroll
    for (int mf = 0; mf < 2; mf++)
#pragma unroll
        for (int nf = 0; nf < 8; nf++)
#pragma unroll
            for (int j = 0; j < 4; j++) acc[mf][nf][j] = 0.0f;

    const int nt = K / 32;

    float4 pa[4], pb[4];
#pragma unroll
    for (int i = 0; i < 4; i++) {
        int f   = tid + i * 256;
        int row = f >> 3;
        int c4  = (f & 7) << 2;
        pa[i] = *(const float4*)(A + (size_t)(m0 + row) * K + c4);
        pb[i] = *(const float4*)(B + (size_t)(n0 + row) * K + c4);
    }
#pragma unroll
    for (int i = 0; i < 4; i++) {
        int f   = tid + i * 256;
        int row = f >> 3;
        int c4  = (f & 7) << 2;
        float* a = As[0] + row * GLD + c4;
        a[0] = __uint_as_float(f2tf32(pa[i].x));
        a[1] = __uint_as_float(f2tf32(pa[i].y));
        a[2] = __uint_as_float(f2tf32(pa[i].z));
        a[3] = __uint_as_float(f2tf32(pa[i].w));
        float* b = Bs[0] + row * GLD + c4;
        b[0] = __uint_as_float(f2tf32(pb[i].x));
        b[1] = __uint_as_float(f2tf32(pb[i].y));
        b[2] = __uint_as_float(f2tf32(pb[i].z));
        b[3] = __uint_as_float(f2tf32(pb[i].w));
    }
    __syncthreads();

    for (int t = 0; t < nt; t++) {
        const int cur = t & 1;
        if (t + 1 < nt) {
            int k0 = (t + 1) * 32;
#pragma unroll
            for (int i = 0; i < 4; i++) {
                int f   = tid + i * 256;
                int row = f >> 3;
                int c4  = (f & 7) << 2;
                pa[i] = *(const float4*)(A + (size_t)(m0 + row) * K + k0 + c4);
                pb[i] = *(const float4*)(B + (size_t)(n0 + row) * K + k0 + c4);
            }
        }

        const float* as = As[cur];
        const float* bs = Bs[cur];
#pragma unroll
        for (int kc = 0; kc < 4; kc++) {
            uint32_t bfr[8][2];
#pragma unroll
            for (int nf = 0; nf < 8; nf++) {
                const float* bp = bs + (wn + nf * 8 + qg) * GLD + kc * 8 + qc;
                bfr[nf][0] = __float_as_uint(bp[0]);
                bfr[nf][1] = __float_as_uint(bp[4]);
            }
#pragma unroll
            for (int mf = 0; mf < 2; mf++) {
                const float* ap = as + (wm + mf * 16 + qg) * GLD + kc * 8 + qc;
                uint32_t afr[4];
                afr[0] = __float_as_uint(ap[0]);
                afr[1] = __float_as_uint(ap[8 * GLD]);
                afr[2] = __float_as_uint(ap[4]);
                afr[3] = __float_as_uint(ap[8 * GLD + 4]);
#pragma unroll
                for (int nf = 0; nf < 8; nf++)
                    mma_tf32(acc[mf][nf], afr, bfr[nf], acc[mf][nf]);
            }
        }

        if (t + 1 < nt) {
            const int nxt = cur ^ 1;
#pragma unroll
            for (int i = 0; i < 4; i++) {
                int f   = tid + i * 256;
                int row = f >> 3;
                int c4  = (f & 7) << 2;
                float* a = As[nxt] + row * GLD + c4;
                a[0] = __uint_as_float(f2tf32(pa[i].x));
                a[1] = __uint_as_float(f2tf32(pa[i].y));
                a[2] = __uint_as_float(f2tf32(pa[i].z));
                a[3] = __uint_as_float(f2tf32(pa[i].w));
                float* b = Bs[nxt] + row * GLD + c4;
                b[0] = __uint_as_float(f2tf32(pb[i].x));
                b[1] = __uint_as_float(f2tf32(pb[i].y));
                b[2] = __uint_as_float(f2tf32(pb[i].z));
                b[3] = __uint_as_float(f2tf32(pb[i].w));
            }
            __syncthreads();
        }
    }

#pragma unroll
    for (int mf = 0; mf < 2; mf++) {
        int row0 = m0 + wm + mf * 16 + qg;
#pragma unroll
        for (int nf = 0; nf < 8; nf++) {
            int col = n0 + wn + nf * 8 + 2 * qc;
            float b0 = bias[col], b1 = bias[col + 1];
            float2 v0 = make_float2(acc[mf][nf][0] + b0, acc[mf][nf][1] + b1);
            float2 v1 = make_float2(acc[mf][nf][2] + b0, acc[mf][nf][3] + b1);
            *(float2*)(C + (size_t)row0 * N + col)       = v0;
            *(float2*)(C + (size_t)(row0 + 8) * N + col) = v1;
        }
    }
}

// ---------------------------------------------------------------------------
// Flash attention, tf32 mma, Br=128 / Bc=64 / Hd=64, 4 warps.
// Each warp owns 32 q-rows (2 m-fragments): K/V fragment LDS + staging + syncs
// amortize over 2x the MMA work vs Br=64.
// QK runs mf-outer (transient s = 32 regs); PV runs kc-outer (V B-frags
// loaded once, shared across both m-frags).
// Smem: Ks[64][LDA], Vs[64][LDB], Ps[128][LDA] (doubles as Q staging).
// ---------------------------------------------------------------------------
#define LDA 68
#define LDB 72
#define FLASH_SMEM ((64 * LDA + 64 * LDB + 128 * LDA) * 4)   // 70656 B

__global__ void __launch_bounds__(128) flash_mma_kernel(
    const float* __restrict__ qkv, float* __restrict__ attn_out)
{
    extern __shared__ float sm[];
    float* Ks = sm;                        // [64][LDA]
    float* Vs = sm + 64 * LDA;             // [64][LDB]
    float* Ps = sm + 64 * LDA + 64 * LDB;  // [128][LDA]  (Q staging, then P)

    const int tid  = threadIdx.x;
    const int lane = tid & 31;
    const int wid  = tid >> 5;
    const int qc   = lane & 3;
    const int qg   = lane >> 2;
    const int h    = blockIdx.y;
    const int q0   = blockIdx.x * 128;
    const int colb = h * HD;

    // ---- Stage Q tile (128x64), scaled + tf32-rounded, into Ps ----
#pragma unroll
    for (int i = 0; i < 16; i++) {
        int f   = tid + i * 128;            // 0..2047 float4 idx
        int row = f >> 4;
        int c4  = (f & 15) << 2;
        float4 a = *(const float4*)(qkv + (size_t)(q0 + row) * LDQKV + colb + c4);
        a.x = __uint_as_float(f2tf32(a.x * 0.125f));
        a.y = __uint_as_float(f2tf32(a.y * 0.125f));
        a.z = __uint_as_float(f2tf32(a.z * 0.125f));
        a.w = __uint_as_float(f2tf32(a.w * 0.125f));
        *(float4*)(Ps + row * LDA + c4) = a;
    }
    __syncthreads();

    // ---- Q fragments to registers: 2 m-frags x 8 k-chunks ----
    uint32_t qf[2][8][4];
#pragma unroll
    for (int mf = 0; mf < 2; mf++) {
        const int r0 = wid * 32 + mf * 16 + qg;
#pragma unroll
        for (int kc = 0; kc < 8; kc++) {
            int d0 = kc * 8;
            qf[mf][kc][0] = __float_as_uint(Ps[r0 * LDA + d0 + qc]);
            qf[mf][kc][1] = __float_as_uint(Ps[(r0 + 8) * LDA + d0 + qc]);
            qf[mf][kc][2] = __float_as_uint(Ps[r0 * LDA + d0 + qc + 4]);
            qf[mf][kc][3] = __float_as_uint(Ps[(r0 + 8) * LDA + d0 + qc + 4]);
        }
    }
    __syncthreads();   // everyone done reading Q from Ps before P overwrites it

    float o[2][8][4];
#pragma unroll
    for (int mf = 0; mf < 2; mf++)
#pragma unroll
        for (int nt = 0; nt < 8; nt++)
#pragma unroll
            for (int j = 0; j < 4; j++) o[mf][nt][j] = 0.0f;
    float m_run[2][2] = { {-CUDART_INF_F, -CUDART_INF_F},
                          {-CUDART_INF_F, -CUDART_INF_F} };
    float l_run[2][2] = { {0.f, 0.f}, {0.f, 0.f} };

    for (int k0 = 0; k0 < S_LEN; k0 += 64) {
        // ---- Stage K, V tiles (64x64 each), tf32-rounded ----
#pragma unroll
        for (int i = 0; i < 8; i++) {
            int f   = tid + i * 128;
            int row = f >> 4;
            int c4  = (f & 15) << 2;
            const float* base = qkv + (size_t)(k0 + row) * LDQKV + colb + c4;
            float4 kv = *(const float4*)(base + D_MODEL);
            kv.x = __uint_as_float(f2tf32(kv.x));
            kv.y = __uint_as_float(f2tf32(kv.y));
            kv.z = __uint_as_float(f2tf32(kv.z));
            kv.w = __uint_as_float(f2tf32(kv.w));
            *(float4*)(Ks + row * LDA + c4) = kv;
            float4 vv = *(const float4*)(base + 2 * D_MODEL);
            vv.x = __uint_as_float(f2tf32(vv.x));
            vv.y = __uint_as_float(f2tf32(vv.y));
            vv.z = __uint_as_float(f2tf32(vv.z));
            vv.w = __uint_as_float(f2tf32(vv.w));
            *(float4*)(Vs + row * LDB + c4) = vv;
        }
        __syncthreads();

        // ---- Per m-fragment: S = Q K^T, online softmax, P store ----
#pragma unroll
        for (int mf = 0; mf < 2; mf++) {
            const int r0 = wid * 32 + mf * 16 + qg;
            const int r1 = r0 + 8;

            float s[8][4];
#pragma unroll
            for (int nt = 0; nt < 8; nt++)
#pragma unroll
                for (int j = 0; j < 4; j++) s[nt][j] = 0.0f;

#pragma unroll
            for (int kc = 0; kc < 8; kc++) {
#pragma unroll
                for (int nt = 0; nt < 8; nt++) {
                    const float* kb = Ks + (nt * 8 + qg) * LDA + kc * 8 + qc;
                    uint32_t b[2];
                    b[0] = __float_as_uint(kb[0]);
                    b[1] = __float_as_uint(kb[4]);
                    mma_tf32(s[nt], qf[mf][kc], b, s[nt]);
                }
            }

            float mlo = -CUDART_INF_F, mhi = -CUDART_INF_F;
#pragma unroll
            for (int nt = 0; nt < 8; nt++) {
                mlo = fmaxf(mlo, fmaxf(s[nt][0], s[nt][1]));
                mhi = fmaxf(mhi, fmaxf(s[nt][2], s[nt][3]));
            }
            mlo = fmaxf(mlo, __shfl_xor_sync(0xffffffffu, mlo, 1));
            mlo = fmaxf(mlo, __shfl_xor_sync(0xffffffffu, mlo, 2));
            mhi = fmaxf(mhi, __shfl_xor_sync(0xffffffffu, mhi, 1));
            mhi = fmaxf(mhi, __shfl_xor_sync(0xffffffffu, mhi, 2));

            float mnlo = fmaxf(m_run[mf][0], mlo);
            float mnhi = fmaxf(m_run[mf][1], mhi);
            float alo  = __expf(m_run[mf][0] - mnlo);
            float ahi  = __expf(m_run[mf][1] - mnhi);
            m_run[mf][0] = mnlo; m_run[mf][1] = mnhi;

            float tlo = 0.0f, thi = 0.0f;
#pragma unroll
            for (int nt = 0; nt < 8; nt++) {
                float p0 = __expf(s[nt][0] - mnlo);
                float p1 = __expf(s[nt][1] - mnlo);
                float p2 = __expf(s[nt][2] - mnhi);
                float p3 = __expf(s[nt][3] - mnhi);
                tlo += p0 + p1;
                thi += p2 + p3;
                uint2 plo = make_uint2(f2tf32(p0), f2tf32(p1));
                uint2 phi = make_uint2(f2tf32(p2), f2tf32(p3));
                *(uint2*)(Ps + r0 * LDA + nt * 8 + 2 * qc) = plo;
                *(uint2*)(Ps + r1 * LDA + nt * 8 + 2 * qc) = phi;
            }
            tlo += __shfl_xor_sync(0xffffffffu, tlo, 1);
            tlo += __shfl_xor_sync(0xffffffffu, tlo, 2);
            thi += __shfl_xor_sync(0xffffffffu, thi, 1);
            thi += __shfl_xor_sync(0xffffffffu, thi, 2);
            l_run[mf][0] = l_run[mf][0] * alo + tlo;
            l_run[mf][1] = l_run[mf][1] * ahi + thi;

#pragma unroll
            for (int nt = 0; nt < 8; nt++) {
                o[mf][nt][0] *= alo; o[mf][nt][1] *= alo;
                o[mf][nt][2] *= ahi; o[mf][nt][3] *= ahi;
            }
        }

        __syncwarp();   // P rows are warp-private; order STS before LDS

        // ---- O += P V  (kc-outer: V B-frags shared by both m-frags) ----
#pragma unroll
        for (int kc = 0; kc < 8; kc++) {
            uint32_t vfr[8][2];
#pragma unroll
            for (int nt = 0; nt < 8; nt++) {
                vfr[nt][0] = __float_as_uint(Vs[(kc * 8 + qc) * LDB + nt * 8 + qg]);
                vfr[nt][1] = __float_as_uint(Vs[(kc * 8 + qc + 4) * LDB + nt * 8 + qg]);
            }
#pragma unroll
            for (int mf = 0; mf < 2; mf++) {
                const int r0 = wid * 32 + mf * 16 + qg;
                const int r1 = r0 + 8;
                uint32_t a[4];
                a[0] = __float_as_uint(Ps[r0 * LDA + kc * 8 + qc]);
                a[1] = __float_as_uint(Ps[r1 * LDA + kc * 8 + qc]);
                a[2] = __float_as_uint(Ps[r0 * LDA + kc * 8 + qc + 4]);
                a[3] = __float_as_uint(Ps[r1 * LDA + kc * 8 + qc + 4]);
#pragma unroll
                for (int nt = 0; nt < 8; nt++)
                    mma_tf32(o[mf][nt], a, vfr[nt], o[mf][nt]);
            }
        }
        __syncthreads();   // done with Ks/Vs (and P) before next staging
    }

    // ---- Epilogue ----
#pragma unroll
    for (int mf = 0; mf < 2; mf++) {
        const int r0 = wid * 32 + mf * 16 + qg;
        const int r1 = r0 + 8;
        float ilo = 1.0f / l_run[mf][0];
        float ihi = 1.0f / l_run[mf][1];
#pragma unroll
        for (int nt = 0; nt < 8; nt++) {
            float2 vlo = make_float2(o[mf][nt][0] * ilo, o[mf][nt][1] * ilo);
            float2 vhi = make_float2(o[mf][nt][2] * ihi, o[mf][nt][3] * ihi);
            *(float2*)(attn_out + (size_t)(q0 + r0) * D_MODEL + colb + nt * 8 + 2 * qc) = vlo;
            *(float2*)(attn_out + (size_t)(q0 + r1) * D_MODEL + colb + nt * 8 + 2 * qc) = vhi;
        }
    }
}

// ---------------------------------------------------------------------------
// Launch: QKV proj (tf32 mma) -> flash attention (tf32 mma) -> out proj
// ---------------------------------------------------------------------------
extern "C" void kernel_launch(void* const* d_in, const int* in_sizes, int n_in,
                              void* d_out, int out_size)
{
    const float* query = (const float*)d_in[0];   // [1,4096,512]
    const float* w_in  = (const float*)d_in[1];   // [1536,512]
    const float* b_in  = (const float*)d_in[2];   // [1536]
    const float* w_out = (const float*)d_in[3];   // [512,512]
    const float* b_out = (const float*)d_in[4];   // [512]
    float*       out   = (float*)d_out;           // [1,4096,512]

    float *qkv, *attn;
    cudaGetSymbolAddress((void**)&qkv,  g_qkv);
    cudaGetSymbolAddress((void**)&attn, g_attn);

    cudaFuncSetAttribute(gemm_tf32_bias,
                         cudaFuncAttributeMaxDynamicSharedMemorySize, GEMM_SMEM);

    // 1) QKV projection: [4096,512] @ [1536,512]^T + bias -> [4096,1536]
    {
        dim3 grid(LDQKV / 128, S_LEN / 128);   // (12, 32)
        gemm_tf32_bias<<<grid, 256, GEMM_SMEM>>>(query, w_in, b_in, qkv,
                                                 S_LEN, LDQKV, D_MODEL);
    }

    // 2) Flash attention per head (tf32 tensor cores, Br=128)
    {
        cudaFuncSetAttribute(flash_mma_kernel,
                             cudaFuncAttributeMaxDynamicSharedMemorySize,
                             FLASH_SMEM);
        dim3 grid(S_LEN / 128, H_NUM);   // (32, 8) = 256 CTAs
        flash_mma_kernel<<<grid, 128, FLASH_SMEM>>>(qkv, attn);
    }

    // 3) Output projection: [4096,512] @ [512,512]^T + bias -> [4096,512]
    {
        dim3 grid(D_MODEL / 128, S_LEN / 128);  // (4, 32)
        gemm_tf32_bias<<<grid, 256, GEMM_SMEM>>>(attn, w_out, b_out, out,
                                                 S_LEN, D_MODEL, D_MODEL);
    }
}